// round 3
// baseline (speedup 1.0000x reference)
#include <cuda_runtime.h>
#include <math.h>

#define BB   8
#define CC   128
#define OO   128
#define HH   64
#define WW   64
#define HW   4096
#define NPIX 32768           // B*H*W
#define CKK  1152            // C*9
#define NOM  27              // 3*K2 channels of the offset/mask conv
#define CCH  32              // channel chunk staged in static smem
#define CHW_ELEMS (NOM*CCH*9)  // 7776 floats = 31.1 KB

// ---------------- device scratch (allocation-free rule: static __device__) -----------
__device__ float g_V[(size_t)CKK * NPIX];          // im2col matrix: V[ck][b*4096+p]
__device__ float4 g_w4[BB * 9 * HW];               // 4 bilinear weights (mask+validity folded)
__device__ int2   g_pos[BB * 9 * HW];              // (y0, x0) unclipped

// ============================================================================
// Kernel 1: 3x3 conv producing 27 channels per pixel, then transform into
// per-(b,k,p) bilinear sampling weights (+softmax mask) and corner position.
// Weights staged in STATIC smem in 4 channel-chunks (31 KB each) -> no
// dynamic-smem attribute needed. All lanes read the same weight address
// simultaneously -> smem broadcast.
// ============================================================================
__global__ __launch_bounds__(256)
void om_kernel(const float* __restrict__ x, const float* __restrict__ w_om,
               const float* __restrict__ b_om) {
    __shared__ float s_w[CHW_ELEMS];   // [oc][c_local][t] = [(oc*32 + cl)*9 + t]
    const int tid = threadIdx.x;

    const int bp = blockIdx.x * 256 + tid;
    const int b = bp >> 12;
    const int p = bp & 4095;
    const int y = p >> 6;
    const int xx = p & 63;

    const float* __restrict__ xb = x + (size_t)(b * CC) * HW;

    float acc[NOM];
#pragma unroll
    for (int i = 0; i < NOM; ++i) acc[i] = 0.f;

    for (int c0 = 0; c0 < CC; c0 += CCH) {
        // stage this chunk's weights: s_w[(oc*CCH + cl)*9 + t] = w_om[oc][c0+cl][t]
        __syncthreads();
        for (int i = tid; i < CHW_ELEMS; i += 256) {
            const int oc = i / (CCH * 9);
            const int rem = i - oc * (CCH * 9);
            const int cl = rem / 9;
            const int t = rem - cl * 9;
            s_w[i] = w_om[(size_t)oc * CKK + (c0 + cl) * 9 + t];
        }
        __syncthreads();

        for (int cl = 0; cl < CCH; ++cl) {
            const float* __restrict__ xc = xb + (c0 + cl) * HW;
            float v[9];
#pragma unroll
            for (int t = 0; t < 9; ++t) {
                const int yy = y + t / 3 - 1;
                const int xc2 = xx + t % 3 - 1;
                const bool ok = (yy >= 0) & (yy < HH) & (xc2 >= 0) & (xc2 < WW);
                v[t] = ok ? __ldg(xc + yy * WW + xc2) : 0.f;
            }
            const float* wc = s_w + cl * 9;
#pragma unroll
            for (int oc = 0; oc < NOM; ++oc) {
                const float* wr = wc + oc * (CCH * 9);
#pragma unroll
                for (int t = 0; t < 9; ++t) acc[oc] = fmaf(wr[t], v[t], acc[oc]);
            }
        }
    }
#pragma unroll
    for (int oc = 0; oc < NOM; ++oc) acc[oc] += __ldg(b_om + oc);

    // softmax over the 9 mask channels (18..26)
    float mx = acc[18];
#pragma unroll
    for (int k = 1; k < 9; ++k) mx = fmaxf(mx, acc[18 + k]);
    float e[9], s = 0.f;
#pragma unroll
    for (int k = 0; k < 9; ++k) { e[k] = expf(acc[18 + k] - mx); s += e[k]; }
    const float inv = 1.f / s;

#pragma unroll
    for (int k = 0; k < 9; ++k) {
        const float m = e[k] * inv;
        // offset channel 2k = dy, 2k+1 = dx  (concat(o1,o2) == om[0:18] directly)
        const float py = (float)(y - 1 + k / 3) + acc[2 * k];
        const float px = (float)(xx - 1 + k % 3) + acc[2 * k + 1];
        const float fy = floorf(py), fx = floorf(px);
        const int y0 = (int)fy, x0 = (int)fx;
        const float wy1 = py - fy, wx1 = px - fx;
        const float wy0 = 1.f - wy1, wx0 = 1.f - wx1;
        const bool vy0 = (y0 >= 0) & (y0 < HH);
        const bool vy1 = (y0 >= -1) & (y0 < HH - 1);
        const bool vx0 = (x0 >= 0) & (x0 < WW);
        const bool vx1 = (x0 >= -1) & (x0 < WW - 1);
        float4 w4;
        w4.x = (vy0 & vx0) ? wy0 * wx0 * m : 0.f;
        w4.y = (vy0 & vx1) ? wy0 * wx1 * m : 0.f;
        w4.z = (vy1 & vx0) ? wy1 * wx0 * m : 0.f;
        w4.w = (vy1 & vx1) ? wy1 * wx1 * m : 0.f;
        const int idx = (b * 9 + k) * HW + p;
        g_w4[idx] = w4;
        g_pos[idx] = make_int2(y0, x0);
    }
}

// ============================================================================
// Kernel 2: materialize V[ck][bp] (bilinear-sampled, mask-weighted im2col).
// Corner weights already carry validity (zeroed), so clamp addresses freely.
// ============================================================================
__global__ __launch_bounds__(256)
void sample_kernel(const float* __restrict__ x) {
    const int ck = blockIdx.y;              // 0..1151
    const int bp = blockIdx.x * 256 + threadIdx.x;
    const int c = ck / 9;
    const int k = ck - c * 9;
    const int b = bp >> 12;
    const int p = bp & 4095;

    const int idx = (b * 9 + k) * HW + p;
    const float4 w4 = g_w4[idx];
    const int2 pos = g_pos[idx];

    const float* __restrict__ xc = x + (size_t)(b * CC + c) * HW;
    const int y0c = min(max(pos.x, 0), HH - 1);
    const int y1c = min(max(pos.x + 1, 0), HH - 1);
    const int x0c = min(max(pos.y, 0), WW - 1);
    const int x1c = min(max(pos.y + 1, 0), WW - 1);

    const float v = w4.x * __ldg(xc + y0c * WW + x0c)
                  + w4.y * __ldg(xc + y0c * WW + x1c)
                  + w4.z * __ldg(xc + y1c * WW + x0c)
                  + w4.w * __ldg(xc + y1c * WW + x1c);
    g_V[(size_t)ck * NPIX + bp] = v;
}

// ============================================================================
// Kernel 3: SGEMM  out[o][bp] = W2[128x1152] * V[1152x32768] + bias
// 128x128 block tile, BK=16, double-buffered smem, 8x8 register microtile.
// ============================================================================
#define BK 16
#define AST 132   // padded row stride for transposed A tile (kills STS bank conflicts)

__global__ __launch_bounds__(256)
void gemm_kernel(const float* __restrict__ Wt,    // weight as [128][1152]
                 const float* __restrict__ bias,
                 float* __restrict__ out) {
    __shared__ float As[2][BK * AST];
    __shared__ float Bs[2][BK * 128];

    const int tid = threadIdx.x;
    const int tx = tid & 15;
    const int ty = tid >> 4;
    const int n0 = blockIdx.x * 128;

    // loader coordinates
    const int ra = tid >> 2;        // 0..63  (row of A; +64 for second load)
    const int qa = tid & 3;         // float4 slot within the 16-wide k chunk
    const int rb = tid >> 5;        // 0..7   (row of B; +8 for second load)
    const int qb = tid & 31;        // float4 column

    float acc[8][8];
#pragma unroll
    for (int i = 0; i < 8; ++i)
#pragma unroll
        for (int j = 0; j < 8; ++j) acc[i][j] = 0.f;

    // ---- prime stage 0 ----
    {
        const int kt = 0;
        float4 a0 = *(const float4*)(Wt + (size_t)ra * CKK + kt + qa * 4);
        float4 a1 = *(const float4*)(Wt + (size_t)(ra + 64) * CKK + kt + qa * 4);
        float4 b0 = *(const float4*)(g_V + (size_t)(kt + rb) * NPIX + n0 + qb * 4);
        float4 b1 = *(const float4*)(g_V + (size_t)(kt + rb + 8) * NPIX + n0 + qb * 4);
        As[0][(qa * 4 + 0) * AST + ra] = a0.x;
        As[0][(qa * 4 + 1) * AST + ra] = a0.y;
        As[0][(qa * 4 + 2) * AST + ra] = a0.z;
        As[0][(qa * 4 + 3) * AST + ra] = a0.w;
        As[0][(qa * 4 + 0) * AST + ra + 64] = a1.x;
        As[0][(qa * 4 + 1) * AST + ra + 64] = a1.y;
        As[0][(qa * 4 + 2) * AST + ra + 64] = a1.z;
        As[0][(qa * 4 + 3) * AST + ra + 64] = a1.w;
        *(float4*)&Bs[0][rb * 128 + qb * 4] = b0;
        *(float4*)&Bs[0][(rb + 8) * 128 + qb * 4] = b1;
    }
    __syncthreads();

    int s = 0;
    const int NIT = CKK / BK;   // 72
    for (int it = 0; it < NIT; ++it) {
        float4 a0n, a1n, b0n, b1n;
        if (it < NIT - 1) {
            const int kt = (it + 1) * BK;
            a0n = *(const float4*)(Wt + (size_t)ra * CKK + kt + qa * 4);
            a1n = *(const float4*)(Wt + (size_t)(ra + 64) * CKK + kt + qa * 4);
            b0n = *(const float4*)(g_V + (size_t)(kt + rb) * NPIX + n0 + qb * 4);
            b1n = *(const float4*)(g_V + (size_t)(kt + rb + 8) * NPIX + n0 + qb * 4);
        }
#pragma unroll
        for (int k = 0; k < BK; ++k) {
            const float4 af0 = *(const float4*)&As[s][k * AST + ty * 8];
            const float4 af1 = *(const float4*)&As[s][k * AST + ty * 8 + 4];
            const float4 bf0 = *(const float4*)&Bs[s][k * 128 + tx * 8];
            const float4 bf1 = *(const float4*)&Bs[s][k * 128 + tx * 8 + 4];
            const float a[8] = {af0.x, af0.y, af0.z, af0.w, af1.x, af1.y, af1.z, af1.w};
            const float bq[8] = {bf0.x, bf0.y, bf0.z, bf0.w, bf1.x, bf1.y, bf1.z, bf1.w};
#pragma unroll
            for (int i = 0; i < 8; ++i)
#pragma unroll
                for (int j = 0; j < 8; ++j)
                    acc[i][j] = fmaf(a[i], bq[j], acc[i][j]);
        }
        if (it < NIT - 1) {
            const int s2 = s ^ 1;
            As[s2][(qa * 4 + 0) * AST + ra] = a0n.x;
            As[s2][(qa * 4 + 1) * AST + ra] = a0n.y;
            As[s2][(qa * 4 + 2) * AST + ra] = a0n.z;
            As[s2][(qa * 4 + 3) * AST + ra] = a0n.w;
            As[s2][(qa * 4 + 0) * AST + ra + 64] = a1n.x;
            As[s2][(qa * 4 + 1) * AST + ra + 64] = a1n.y;
            As[s2][(qa * 4 + 2) * AST + ra + 64] = a1n.z;
            As[s2][(qa * 4 + 3) * AST + ra + 64] = a1n.w;
            *(float4*)&Bs[s2][rb * 128 + qb * 4] = b0n;
            *(float4*)&Bs[s2][(rb + 8) * 128 + qb * 4] = b1n;
        }
        __syncthreads();
        s ^= 1;
    }

    // ---- epilogue: add bias, write out[b][o][p] ----
    const int b = n0 >> 12;          // 4096 % 128 == 0 -> whole tile in one batch
    const int p0 = n0 & 4095;
#pragma unroll
    for (int i = 0; i < 8; ++i) {
        const int o = ty * 8 + i;
        const float bv = __ldg(bias + o);
        float* op = out + ((size_t)(b * OO + o)) * HW + p0 + tx * 8;
        float4 r0, r1;
        r0.x = acc[i][0] + bv; r0.y = acc[i][1] + bv;
        r0.z = acc[i][2] + bv; r0.w = acc[i][3] + bv;
        r1.x = acc[i][4] + bv; r1.y = acc[i][5] + bv;
        r1.z = acc[i][6] + bv; r1.w = acc[i][7] + bv;
        *(float4*)op = r0;
        *(float4*)(op + 4) = r1;
    }
}

// ============================================================================
extern "C" void kernel_launch(void* const* d_in, const int* in_sizes, int n_in,
                              void* d_out, int out_size) {
    const float* x      = (const float*)d_in[0];   // (8,128,64,64)
    const float* w_om   = (const float*)d_in[1];   // (27,128,3,3)
    const float* b_om   = (const float*)d_in[2];   // (27,)
    const float* weight = (const float*)d_in[3];   // (128,128,3,3) -> [128][1152]
    const float* bias   = (const float*)d_in[4];   // (128,)
    float* out = (float*)d_out;                    // (8,128,64,64)

    om_kernel<<<NPIX / 256, 256>>>(x, w_om, b_om);
    sample_kernel<<<dim3(NPIX / 256, CKK), 256>>>(x);
    gemm_kernel<<<NPIX / 128, 256>>>(weight, bias, out);
}